// round 2
// baseline (speedup 1.0000x reference)
#include <cuda_runtime.h>
#include <cstdint>

// Problem constants (from reference)
#define NUM_STUDENTS 50000
#define NUM_PROBLEMS 10000
#define EMBED_DIM    64
#define NNZ_EDGES    3200000

// d=64 floats = 16 float4 chunks per row
#define CHUNKS 16

// Output layout (floats):
//   [0)                      student_embeds_c   : 50000*64
//   [3,200,000)              student_embeds_ic  : 50000*64
//   [6,400,000)              problem_embeds_c   : 10000*64
//   [7,040,000)              problem_embeds_ic  : 10000*64
// total 7,680,000 floats

__device__ __forceinline__ void red_add_f4(float4* addr, float4 v) {
    asm volatile("red.global.add.v4.f32 [%0], {%1, %2, %3, %4};"
                 :: "l"(addr), "f"(v.x), "f"(v.y), "f"(v.z), "f"(v.w)
                 : "memory");
}

__global__ void zero_out_kernel(float4* __restrict__ out, int n_f4) {
    int i = blockIdx.x * blockDim.x + threadIdx.x;
    if (i < n_f4) out[i] = make_float4(0.f, 0.f, 0.f, 0.f);
}

// One pass over an edge list computes BOTH directions:
//   out_s[row] += val * p_emb[col]     (A  @ problem_embeds)
//   out_p[col] += val * s_emb[row]     (A^T @ student_embeds)
// Thread mapping: idx = e*16 + c ; 16 threads per edge, chunk c in [0,16).
__global__ void spmm_dual_kernel(const int*   __restrict__ rows,
                                 const int*   __restrict__ cols,
                                 const float* __restrict__ vals,
                                 const float4* __restrict__ s_emb,   // [NUM_STUDENTS*16]
                                 const float4* __restrict__ p_emb,   // [NUM_PROBLEMS*16]
                                 float4* __restrict__ out_s,         // [NUM_STUDENTS*16]
                                 float4* __restrict__ out_p,         // [NUM_PROBLEMS*16]
                                 int nnz) {
    unsigned int idx = blockIdx.x * blockDim.x + threadIdx.x;
    unsigned int e = idx >> 4;
    unsigned int c = idx & 15u;
    if (e >= (unsigned int)nnz) return;

    int   r  = rows[e];
    int   cl = cols[e];
    float v  = vals[e];

    // gather (L2-resident random access, coalesced 256B per edge across 16 threads)
    float4 pv = __ldg(&p_emb[(unsigned)cl * CHUNKS + c]);
    float4 sv = __ldg(&s_emb[(unsigned)r  * CHUNKS + c]);

    float4 to_s = make_float4(v * pv.x, v * pv.y, v * pv.z, v * pv.w);
    float4 to_p = make_float4(v * sv.x, v * sv.y, v * sv.z, v * sv.w);

    red_add_f4(&out_s[(unsigned)r  * CHUNKS + c], to_s);
    red_add_f4(&out_p[(unsigned)cl * CHUNKS + c], to_p);
}

extern "C" void kernel_launch(void* const* d_in, const int* in_sizes, int n_in,
                              void* d_out, int out_size) {
    const float* student_embeds = (const float*)d_in[0];
    const float* problem_embeds = (const float*)d_in[1];
    const int*   a_rows  = (const int*)d_in[2];
    const int*   a_cols  = (const int*)d_in[3];
    const float* a_vals  = (const float*)d_in[4];
    const int*   ia_rows = (const int*)d_in[5];
    const int*   ia_cols = (const int*)d_in[6];
    const float* ia_vals = (const float*)d_in[7];

    float* out = (float*)d_out;

    const int nnz = in_sizes[2];  // 3,200,000

    float* out_student_c  = out;                                  // [50000,64]
    float* out_student_ic = out + NUM_STUDENTS * EMBED_DIM;       // [50000,64]
    float* out_problem_c  = out + 2 * NUM_STUDENTS * EMBED_DIM;   // [10000,64]
    float* out_problem_ic = out + 2 * NUM_STUDENTS * EMBED_DIM
                                + NUM_PROBLEMS * EMBED_DIM;       // [10000,64]

    // 1) zero the output (harness poisons with 0xAA)
    {
        int n_f4 = out_size / 4;
        int threads = 256;
        int blocks = (n_f4 + threads - 1) / threads;
        zero_out_kernel<<<blocks, threads>>>((float4*)d_out, n_f4);
    }

    // 2) dual-direction SpMM for each edge list
    {
        int threads = 256;
        long long total = (long long)nnz * CHUNKS;
        int blocks = (int)((total + threads - 1) / threads);

        spmm_dual_kernel<<<blocks, threads>>>(
            a_rows, a_cols, a_vals,
            (const float4*)student_embeds, (const float4*)problem_embeds,
            (float4*)out_student_c, (float4*)out_problem_c, nnz);

        spmm_dual_kernel<<<blocks, threads>>>(
            ia_rows, ia_cols, ia_vals,
            (const float4*)student_embeds, (const float4*)problem_embeds,
            (float4*)out_student_ic, (float4*)out_problem_ic, nnz);
    }
}